// round 5
// baseline (speedup 1.0000x reference)
#include <cuda_runtime.h>
#include <cuda_bf16.h>
#include <math.h>
#include <stddef.h>
#include <stdint.h>

// ---------------------------------------------------------------------------
// Problem constants
// ---------------------------------------------------------------------------
#define B_TOK   16384
#define D_IN    512
#define D_OUT   64
#define H1      64
#define H2      32
#define GH      32
#define NEXP    6
#define NCAT    480
#define NCATP   512
#define LN_EPS  1e-5f

// ---------------------------------------------------------------------------
// Device scratch
// ---------------------------------------------------------------------------
__device__ __align__(16) __nv_bfloat16 g_vhi[(size_t)B_TOK * D_IN];
__device__ __align__(16) __nv_bfloat16 g_vlo[(size_t)B_TOK * D_IN];
__device__ __align__(16) __nv_bfloat16 g_wthi[NCATP * D_IN];   // [n][k]
__device__ __align__(16) __nv_bfloat16 g_wtlo[NCATP * D_IN];
__device__ float g_bc[NCATP];
__device__ __align__(16) float g_HT[(size_t)NCATP * B_TOK];    // H transposed [col][token]

__device__ __forceinline__ uint32_t smem_u32(const void* p) {
    uint32_t a;
    asm("{ .reg .u64 t; cvta.to.shared.u64 t, %1; cvt.u32.u64 %0, t; }" : "=r"(a) : "l"(p));
    return a;
}

// ---------------------------------------------------------------------------
// Kernel: convert v -> bf16 hi/lo (error-free split)
// ---------------------------------------------------------------------------
__global__ __launch_bounds__(256) void conv_v_kernel(const float* __restrict__ v) {
    size_t i = ((size_t)blockIdx.x * 256 + threadIdx.x) * 4;
    float4 x = *(const float4*)(v + i);
    __nv_bfloat16 h0 = __float2bfloat16_rn(x.x), h1 = __float2bfloat16_rn(x.y);
    __nv_bfloat16 h2 = __float2bfloat16_rn(x.z), h3 = __float2bfloat16_rn(x.w);
    __nv_bfloat16 l0 = __float2bfloat16_rn(x.x - __bfloat162float(h0));
    __nv_bfloat16 l1 = __float2bfloat16_rn(x.y - __bfloat162float(h1));
    __nv_bfloat16 l2 = __float2bfloat16_rn(x.z - __bfloat162float(h2));
    __nv_bfloat16 l3 = __float2bfloat16_rn(x.w - __bfloat162float(h3));
    __nv_bfloat162* ph = (__nv_bfloat162*)(g_vhi + i);
    __nv_bfloat162* pl = (__nv_bfloat162*)(g_vlo + i);
    ph[0] = __nv_bfloat162(h0, h1); ph[1] = __nv_bfloat162(h2, h3);
    pl[0] = __nv_bfloat162(l0, l1); pl[1] = __nv_bfloat162(l2, l3);
}

// ---------------------------------------------------------------------------
// Kernel: pack transposed layer-1 weights [n][k] bf16 hi/lo + bias (padded)
// ---------------------------------------------------------------------------
__global__ __launch_bounds__(256) void pack_w_kernel(
    const float* __restrict__ sw1, const float* __restrict__ sb1,
    const float* __restrict__ gw1, const float* __restrict__ gb1,
    const float* __restrict__ sgw1, const float* __restrict__ sgb1,
    const float* __restrict__ ggw1, const float* __restrict__ ggb1) {
    int idx = blockIdx.x * 256 + threadIdx.x;   // over 512*512
    int n = idx >> 9, k = idx & 511;
    float w = 0.f;
    if (n < 384) {
        int e = n >> 6, j = n & 63;
        w = (e < 2) ? sw1[((size_t)e * D_IN + k) * 64 + j]
                    : gw1[((size_t)(e - 2) * D_IN + k) * 64 + j];
    } else if (n < 480) {
        int m = n - 384, s = m >> 5, j = m & 31;
        w = (s == 0) ? sgw1[k * 32 + j]
                     : ggw1[((size_t)(s - 1) * D_IN + k) * 32 + j];
    }
    __nv_bfloat16 hi = __float2bfloat16_rn(w);
    g_wthi[idx] = hi;
    g_wtlo[idx] = __float2bfloat16_rn(w - __bfloat162float(hi));
    if (idx < NCATP) {
        float b = 0.f;
        if (idx < 384) {
            int e = idx >> 6, j = idx & 63;
            b = (e < 2) ? sb1[e * 64 + j] : gb1[(e - 2) * 64 + j];
        } else if (idx < 480) {
            int m = idx - 384, s = m >> 5, j = m & 31;
            b = (s == 0) ? sgb1[j] : ggb1[(s - 1) * GH + j];
        }
        g_bc[idx] = b;
    }
}

// ---------------------------------------------------------------------------
// Kernel: H^T = silu(v @ W + b)^T via mma.sync bf16 split (3 passes),
// 2-stage cp.async pipeline, K chunks of 32.
// CTA 128x128, warps 2(M)x4(N).
// ---------------------------------------------------------------------------
#define KCH2    32
#define RS2     80                          // bytes per smem row (64 + 16 pad)
#define OPB     (128 * RS2)                 // 10240 per operand per stage
#define STAGE_B (4 * OPB)                   // 40960
#define SMO_BIAS (2 * STAGE_B)              // 81920
#define GEMM_SMEM (SMO_BIAS + 512)
#define STG_STRIDE 136                      // floats, epilogue stage [col][row]
#define NCHUNK  (D_IN / KCH2)               // 16

#define CPASYNC16(dst, src) \
    asm volatile("cp.async.cg.shared.global [%0], [%1], 16;" :: "r"(dst), "l"(src))

__device__ __forceinline__ void ldsm_x4(uint32_t* r, uint32_t a) {
    asm volatile("ldmatrix.sync.aligned.m8n8.x4.shared.b16 {%0,%1,%2,%3}, [%4];"
                 : "=r"(r[0]), "=r"(r[1]), "=r"(r[2]), "=r"(r[3]) : "r"(a));
}
__device__ __forceinline__ void mma_bf16(float* c, const uint32_t* a, uint32_t b0, uint32_t b1) {
    asm volatile(
        "mma.sync.aligned.m16n8k16.row.col.f32.bf16.bf16.f32 "
        "{%0,%1,%2,%3}, {%4,%5,%6,%7}, {%8,%9}, {%0,%1,%2,%3};"
        : "+f"(c[0]), "+f"(c[1]), "+f"(c[2]), "+f"(c[3])
        : "r"(a[0]), "r"(a[1]), "r"(a[2]), "r"(a[3]), "r"(b0), "r"(b1));
}

__global__ void __launch_bounds__(256, 2) gemm1_mma_kernel() {
    extern __shared__ char smem[];
    const uint32_t sb = smem_u32(smem);
    const int tid  = threadIdx.x;
    const int lane = tid & 31;
    const int warp = tid >> 5;
    const int wm = warp >> 2;
    const int wn = warp & 3;
    const int bm = blockIdx.y * 128;
    const int bn = blockIdx.x * 128;

    if (tid < 128) ((float*)(smem + SMO_BIAS))[tid] = g_bc[bn + tid];

    // cp.async geometry: per op 128 rows x 64B = 512 x 16B segs, 2 per thread
    const int r0 = tid >> 2, r1 = (tid + 256) >> 2;
    const int s4 = (tid & 3) * 16;          // byte seg within 64B row-chunk

    // ldmatrix lane geometry
    const int mi = lane >> 3;
    const int a_row = (lane & 7) + ((mi & 1) << 3);
    const int a_kb  = (mi >= 2) ? 16 : 0;
    const int b_row = (lane & 7) + ((mi >= 2) ? 8 : 0);
    const int b_kb  = (mi & 1) ? 16 : 0;

    float acc[4][4][4];
#pragma unroll
    for (int i = 0; i < 4; i++)
#pragma unroll
        for (int j = 0; j < 4; j++)
#pragma unroll
            for (int u = 0; u < 4; u++) acc[i][j][u] = 0.f;

    // chunk loader
    auto load_chunk = [&](int ch, int stg) {
        const int k0 = ch * KCH2;
        const uint32_t base = sb + stg * STAGE_B;
        const __nv_bfloat16* sa0 = g_vhi  + (size_t)(bm + r0) * D_IN + k0 + (s4 >> 1);
        const __nv_bfloat16* sa1 = g_vhi  + (size_t)(bm + r1) * D_IN + k0 + (s4 >> 1);
        const __nv_bfloat16* sb0 = g_wthi + (size_t)(bn + r0) * D_IN + k0 + (s4 >> 1);
        const __nv_bfloat16* sb1_ = g_wthi + (size_t)(bn + r1) * D_IN + k0 + (s4 >> 1);
        uint32_t d0 = r0 * RS2 + s4, d1 = r1 * RS2 + s4;
        CPASYNC16(base + 0 * OPB + d0, sa0);
        CPASYNC16(base + 0 * OPB + d1, sa1);
        CPASYNC16(base + 1 * OPB + d0, sa0 + (g_vlo - g_vhi));
        CPASYNC16(base + 1 * OPB + d1, sa1 + (g_vlo - g_vhi));
        CPASYNC16(base + 2 * OPB + d0, sb0);
        CPASYNC16(base + 2 * OPB + d1, sb1_);
        CPASYNC16(base + 3 * OPB + d0, sb0 + (g_wtlo - g_wthi));
        CPASYNC16(base + 3 * OPB + d1, sb1_ + (g_wtlo - g_wthi));
    };

    load_chunk(0, 0);
    asm volatile("cp.async.commit_group;");

    for (int ch = 0; ch < NCHUNK; ch++) {
        const int cur = ch & 1;
        if (ch + 1 < NCHUNK) {
            load_chunk(ch + 1, (ch + 1) & 1);
            asm volatile("cp.async.commit_group;");
            asm volatile("cp.async.wait_group 1;");
        } else {
            asm volatile("cp.async.wait_group 0;");
        }
        __syncthreads();

        const uint32_t stgb = sb + cur * STAGE_B;
        const uint32_t aAddr0 = stgb + 0 * OPB + (wm * 64 + a_row) * RS2 + a_kb;
        const uint32_t alAdd  = 1 * OPB;
        const uint32_t bAddr0 = stgb + 2 * OPB + (wn * 32 + b_row) * RS2 + b_kb;
        const uint32_t blAdd  = 1 * OPB;

#pragma unroll
        for (int kt = 0; kt < 2; kt++) {
            const uint32_t ka = kt * 32;
            uint32_t ah[4][4], al[4][4], bh[2][4], bl[2][4];
#pragma unroll
            for (int mt = 0; mt < 4; mt++)
                ldsm_x4(ah[mt], aAddr0 + mt * (16 * RS2) + ka);
#pragma unroll
            for (int h = 0; h < 2; h++)
                ldsm_x4(bh[h], bAddr0 + h * (16 * RS2) + ka);
#pragma unroll
            for (int mt = 0; mt < 4; mt++)
#pragma unroll
                for (int nt = 0; nt < 4; nt++)
                    mma_bf16(acc[mt][nt], ah[mt], bh[nt >> 1][(nt & 1) * 2], bh[nt >> 1][(nt & 1) * 2 + 1]);
#pragma unroll
            for (int h = 0; h < 2; h++)
                ldsm_x4(bl[h], bAddr0 + blAdd + h * (16 * RS2) + ka);
#pragma unroll
            for (int mt = 0; mt < 4; mt++)
#pragma unroll
                for (int nt = 0; nt < 4; nt++)
                    mma_bf16(acc[mt][nt], ah[mt], bl[nt >> 1][(nt & 1) * 2], bl[nt >> 1][(nt & 1) * 2 + 1]);
#pragma unroll
            for (int mt = 0; mt < 4; mt++)
                ldsm_x4(al[mt], aAddr0 + alAdd + mt * (16 * RS2) + ka);
#pragma unroll
            for (int mt = 0; mt < 4; mt++)
#pragma unroll
                for (int nt = 0; nt < 4; nt++)
                    mma_bf16(acc[mt][nt], al[mt], bh[nt >> 1][(nt & 1) * 2], bh[nt >> 1][(nt & 1) * 2 + 1]);
        }
        __syncthreads();
    }

    // Epilogue: bias + silu -> smem stage [col][row] -> coalesced g_HT writes
    {
        float* stg = (float*)smem;
        const float* bias = (const float*)(smem + SMO_BIAS);
#pragma unroll
        for (int mt = 0; mt < 4; mt++) {
#pragma unroll
            for (int nt = 0; nt < 4; nt++) {
#pragma unroll
                for (int u = 0; u < 4; u++) {
                    int row = wm * 64 + mt * 16 + (lane >> 2) + ((u >> 1) << 3);
                    int col = wn * 32 + nt * 8 + 2 * (lane & 3) + (u & 1);
                    float x = acc[mt][nt][u] + bias[col];
                    stg[col * STG_STRIDE + row] = x / (1.f + __expf(-x));
                }
            }
        }
        __syncthreads();
#pragma unroll
        for (int cl = 0; cl < 16; cl++) {
            int col = warp * 16 + cl;
            int gc = bn + col;
            if (gc < NCAT) {
                float4 val = *(float4*)&stg[col * STG_STRIDE + lane * 4];
                *(float4*)(g_HT + (size_t)gc * B_TOK + bm + lane * 4) = val;
            }
        }
    }
}

// ---------------------------------------------------------------------------
// Kernel: tail3 — slot-per-CTA (both experts), token-per-thread, smem-staged.
// grid (B/128, 3), 128 threads. Writes final out directly (no combine).
// planes: 0=group0 (e 2,3), 1=group1 (e 4,5), 2=shared (e 0,1)
// ---------------------------------------------------------------------------
// smem layout (floats):
#define T3_H1   0                        // 8192 : h1s[64][128]
#define T3_ZAC  8192                     // 8256 : zac[64][129]
#define T3_GS   16448                    // 4096 : gs[32][128]
#define T3_W2   20544                    // 2048
#define T3_W3   22592                    // 2048
#define T3_B2   24640                    // 32
#define T3_B3   24672                    // 64
#define T3_GM   24736                    // 64
#define T3_BT   24800                    // 64
#define T3_GW   24864                    // 64
#define T3_GB   24928                    // 2
#define T3_FLOATS 24930
#define T3_SMEM (T3_FLOATS * 4)

__global__ __launch_bounds__(128) void tail3_kernel(
    const float* __restrict__ sw2, const float* __restrict__ sb2,
    const float* __restrict__ sw3, const float* __restrict__ sb3,
    const float* __restrict__ sgam, const float* __restrict__ sbet,
    const float* __restrict__ sgw2, const float* __restrict__ sgb2,
    const float* __restrict__ gw2, const float* __restrict__ gb2,
    const float* __restrict__ gw3, const float* __restrict__ gb3,
    const float* __restrict__ ggam, const float* __restrict__ gbet,
    const float* __restrict__ ggw2, const float* __restrict__ ggb2,
    float* __restrict__ out) {
    extern __shared__ float sm[];
    float* h1s = sm + T3_H1;
    float* zac = sm + T3_ZAC;
    float* gs  = sm + T3_GS;
    float* w2s = sm + T3_W2;
    float* w3s = sm + T3_W3;
    float* b2s = sm + T3_B2;
    float* b3s = sm + T3_B3;
    float* gms = sm + T3_GM;
    float* bts = sm + T3_BT;
    float* gws = sm + T3_GW;
    float* gbs = sm + T3_GB;

    const int p   = blockIdx.y;
    const int tid = threadIdx.x;
    const int t0  = blockIdx.x * 128;
    const int e_base = (p == 2) ? 0 : ((p == 0) ? 2 : 4);
    const int gslot  = (p == 2) ? 0 : (p + 1);

    // stage gate rows [32][128] + gate weights
#pragma unroll
    for (int k = 0; k < 8; k++) {
        int lin = tid + k * 128;
        int i = lin >> 5, q = lin & 31;
        float4 val = *(const float4*)(g_HT + (size_t)(384 + gslot * 32 + i) * B_TOK + t0 + q * 4);
        *(float4*)&gs[i * 128 + q * 4] = val;
    }
    if (tid < 64) gws[tid] = (gslot == 0) ? sgw2[tid] : ggw2[(gslot - 1) * 64 + tid];
    if (tid < 2)  gbs[tid] = (gslot == 0) ? sgb2[tid] : ggb2[(gslot - 1) * 2 + tid];
    __syncthreads();

    // gate softmax over the slot's 2 experts (per token)
    float l0 = gbs[0], l1 = gbs[1];
#pragma unroll 8
    for (int i = 0; i < GH; i++) {
        float hg = gs[i * 128 + tid];
        l0 += hg * gws[i * 2];
        l1 += hg * gws[i * 2 + 1];
    }
    float mx = fmaxf(l0, l1);
    float ea = __expf(l0 - mx), eb = __expf(l1 - mx);
    float inv_s = 1.f / (ea + eb);
    float wgate[2] = { ea * inv_s, eb * inv_s };

    for (int sub = 0; sub < 2; sub++) {
        const int e = e_base + sub;
        __syncthreads();   // protect h1s/w2s/w3s/params from previous use

        // stage h1 rows [64][128]
#pragma unroll
        for (int k = 0; k < 16; k++) {
            int lin = tid + k * 128;
            int i = lin >> 5, q = lin & 31;
            float4 val = *(const float4*)(g_HT + (size_t)(e * 64 + i) * B_TOK + t0 + q * 4);
            *(float4*)&h1s[i * 128 + q * 4] = val;
        }
        // stage weights
        const float* w2src = (e < 2) ? (sw2 + (size_t)e * 2048) : (gw2 + (size_t)(e - 2) * 2048);
        const float* w3src = (e < 2) ? (sw3 + (size_t)e * 2048) : (gw3 + (size_t)(e - 2) * 2048);
        for (int i = tid; i < 2048; i += 128) { w2s[i] = w2src[i]; w3s[i] = w3src[i]; }
        if (tid < H2) b2s[tid] = (e < 2) ? sb2[e * 32 + tid] : gb2[(e - 2) * 32 + tid];
        if (tid < D_OUT) {
            b3s[tid] = (e < 2) ? sb3[e * 64 + tid]  : gb3[(e - 2) * 64 + tid];
            gms[tid] = (e < 2) ? sgam[e * 64 + tid] : ggam[(e - 2) * 64 + tid];
            bts[tid] = (e < 2) ? sbet[e * 64 + tid] : gbet[(e - 2) * 64 + tid];
        }
        __syncthreads();

        // layer 2: h2[32] = silu(h1 @ W2 + b2)
        float h2[H2];
#pragma unroll
        for (int j = 0; j < H2; j++) h2[j] = b2s[j];
#pragma unroll 4
        for (int i = 0; i < H1; i++) {
            float a = h1s[i * 128 + tid];
            const float4* w4 = (const float4*)&w2s[i * H2];
#pragma unroll
            for (int j4 = 0; j4 < 8; j4++) {
                float4 w = w4[j4];
                h2[j4 * 4 + 0] += a * w.x;
                h2[j4 * 4 + 1] += a * w.y;
                h2[j4 * 4 + 2] += a * w.z;
                h2[j4 * 4 + 3] += a * w.w;
            }
        }
#pragma unroll
        for (int j = 0; j < H2; j++) h2[j] = h2[j] / (1.f + __expf(-h2[j]));

        // layer 3: o[64] = h2 @ W3 + b3
        float o[D_OUT];
#pragma unroll
        for (int j = 0; j < D_OUT; j++) o[j] = b3s[j];
#pragma unroll 2
        for (int i = 0; i < H2; i++) {
            float h = h2[i];
            const float4* w4 = (const float4*)&w3s[i * D_OUT];
#pragma unroll
            for (int j4 = 0; j4 < 16; j4++) {
                float4 w = w4[j4];
                o[j4 * 4 + 0] += h * w.x;
                o[j4 * 4 + 1] += h * w.y;
                o[j4 * 4 + 2] += h * w.z;
                o[j4 * 4 + 3] += h * w.w;
            }
        }

        // LayerNorm (per-thread register reduction)
        float s1 = 0.f;
#pragma unroll
        for (int j = 0; j < D_OUT; j++) s1 += o[j];
        float mu = s1 * (1.f / 64.f);
        float s2 = 0.f;
#pragma unroll
        for (int j = 0; j < D_OUT; j++) { float d = o[j] - mu; s2 += d * d; }
        float x = s2 * (1.f / 64.f) + LN_EPS;
        float rinv = rsqrtf(x);
        rinv = rinv * (1.5f - 0.5f * x * rinv * rinv);   // Newton refine

        float wg = wgate[sub];
        if (sub == 0) {
#pragma unroll
            for (int j = 0; j < D_OUT; j++)
                zac[j * 129 + tid] = wg * (gms[j] * (o[j] - mu) * rinv + bts[j]);
        } else {
#pragma unroll
            for (int j = 0; j < D_OUT; j++)
                zac[j * 129 + tid] += wg * (gms[j] * (o[j] - mu) * rinv + bts[j]);
        }
    }
    __syncthreads();

    // transpose-store final plane: out[p][t0..t0+127][0..63]
    float* obase = out + ((size_t)p * B_TOK + t0) * D_OUT;
#pragma unroll
    for (int r = 0; r < 16; r++) {
        int lin = tid + r * 128;           // float4 index over 8192 floats
        int tok = lin >> 4;
        int j0  = (lin & 15) * 4;
        float4 val;
        val.x = zac[(j0 + 0) * 129 + tok];
        val.y = zac[(j0 + 1) * 129 + tok];
        val.z = zac[(j0 + 2) * 129 + tok];
        val.w = zac[(j0 + 3) * 129 + tok];
        *(float4*)(obase + lin * 4) = val;
    }
}

// ---------------------------------------------------------------------------
// Launch
// ---------------------------------------------------------------------------
extern "C" void kernel_launch(void* const* d_in, const int* in_sizes, int n_in,
                              void* d_out, int out_size) {
    (void)in_sizes; (void)n_in; (void)out_size;
    const float* v    = (const float*)d_in[0];
    const float* sw1  = (const float*)d_in[1];
    const float* sb1  = (const float*)d_in[2];
    const float* sw2  = (const float*)d_in[3];
    const float* sb2  = (const float*)d_in[4];
    const float* sw3  = (const float*)d_in[5];
    const float* sb3  = (const float*)d_in[6];
    const float* sgam = (const float*)d_in[7];
    const float* sbet = (const float*)d_in[8];
    const float* sgw1 = (const float*)d_in[9];
    const float* sgb1 = (const float*)d_in[10];
    const float* sgw2 = (const float*)d_in[11];
    const float* sgb2 = (const float*)d_in[12];
    const float* gw1  = (const float*)d_in[13];
    const float* gb1  = (const float*)d_in[14];
    const float* gw2  = (const float*)d_in[15];
    const float* gb2  = (const float*)d_in[16];
    const float* gw3  = (const float*)d_in[17];
    const float* gb3  = (const float*)d_in[18];
    const float* ggam = (const float*)d_in[19];
    const float* gbet = (const float*)d_in[20];
    const float* ggw1 = (const float*)d_in[21];
    const float* ggb1 = (const float*)d_in[22];
    const float* ggw2 = (const float*)d_in[23];
    const float* ggb2 = (const float*)d_in[24];
    float* out = (float*)d_out;

    conv_v_kernel<<<(B_TOK * D_IN / 4 + 255) / 256, 256>>>(v);
    pack_w_kernel<<<(NCATP * D_IN + 255) / 256, 256>>>(sw1, sb1, gw1, gb1, sgw1, sgb1, ggw1, ggb1);

    cudaFuncSetAttribute(gemm1_mma_kernel, cudaFuncAttributeMaxDynamicSharedMemorySize, GEMM_SMEM);
    dim3 g1(NCATP / 128, B_TOK / 128);
    gemm1_mma_kernel<<<g1, 256, GEMM_SMEM>>>();

    cudaFuncSetAttribute(tail3_kernel, cudaFuncAttributeMaxDynamicSharedMemorySize, T3_SMEM);
    dim3 g2(B_TOK / 128, 3);
    tail3_kernel<<<g2, 128, T3_SMEM>>>(sw2, sb2, sw3, sb3, sgam, sbet, sgw2, sgb2,
                                       gw2, gb2, gw3, gb3, ggam, gbet, ggw2, ggb2, out);
}

// round 6
// speedup vs baseline: 1.0702x; 1.0702x over previous
#include <cuda_runtime.h>
#include <cuda_bf16.h>
#include <math.h>
#include <stddef.h>
#include <stdint.h>

// ---------------------------------------------------------------------------
// Problem constants
// ---------------------------------------------------------------------------
#define B_TOK   16384
#define D_IN    512
#define D_OUT   64
#define H1      64
#define H2      32
#define GH      32
#define NEXP    6
#define NCAT    480
#define NCATP   512
#define LN_EPS  1e-5f

// ---------------------------------------------------------------------------
// Device scratch
// ---------------------------------------------------------------------------
__device__ __align__(16) __nv_bfloat16 g_vhi[(size_t)B_TOK * D_IN];
__device__ __align__(16) __nv_bfloat16 g_vlo[(size_t)B_TOK * D_IN];
__device__ __align__(16) __nv_bfloat16 g_wthi[NCATP * D_IN];   // [n][k]
__device__ __align__(16) __nv_bfloat16 g_wtlo[NCATP * D_IN];
__device__ float g_bc[NCATP];
__device__ __align__(16) float g_HT[(size_t)NCATP * B_TOK];    // H transposed [col][token]

__device__ __forceinline__ uint32_t smem_u32(const void* p) {
    uint32_t a;
    asm("{ .reg .u64 t; cvta.to.shared.u64 t, %1; cvt.u32.u64 %0, t; }" : "=r"(a) : "l"(p));
    return a;
}

// ---------------------------------------------------------------------------
// Kernel: convert v -> bf16 hi/lo (error-free split)
// ---------------------------------------------------------------------------
__global__ __launch_bounds__(256) void conv_v_kernel(const float* __restrict__ v) {
    size_t i = ((size_t)blockIdx.x * 256 + threadIdx.x) * 4;
    float4 x = *(const float4*)(v + i);
    __nv_bfloat16 h0 = __float2bfloat16_rn(x.x), h1 = __float2bfloat16_rn(x.y);
    __nv_bfloat16 h2 = __float2bfloat16_rn(x.z), h3 = __float2bfloat16_rn(x.w);
    __nv_bfloat16 l0 = __float2bfloat16_rn(x.x - __bfloat162float(h0));
    __nv_bfloat16 l1 = __float2bfloat16_rn(x.y - __bfloat162float(h1));
    __nv_bfloat16 l2 = __float2bfloat16_rn(x.z - __bfloat162float(h2));
    __nv_bfloat16 l3 = __float2bfloat16_rn(x.w - __bfloat162float(h3));
    __nv_bfloat162* ph = (__nv_bfloat162*)(g_vhi + i);
    __nv_bfloat162* pl = (__nv_bfloat162*)(g_vlo + i);
    ph[0] = __nv_bfloat162(h0, h1); ph[1] = __nv_bfloat162(h2, h3);
    pl[0] = __nv_bfloat162(l0, l1); pl[1] = __nv_bfloat162(l2, l3);
}

// ---------------------------------------------------------------------------
// Kernel: pack transposed layer-1 weights [n][k] bf16 hi/lo + bias (padded)
// ---------------------------------------------------------------------------
__global__ __launch_bounds__(256) void pack_w_kernel(
    const float* __restrict__ sw1, const float* __restrict__ sb1,
    const float* __restrict__ gw1, const float* __restrict__ gb1,
    const float* __restrict__ sgw1, const float* __restrict__ sgb1,
    const float* __restrict__ ggw1, const float* __restrict__ ggb1) {
    int idx = blockIdx.x * 256 + threadIdx.x;   // over 512*512
    int n = idx >> 9, k = idx & 511;
    float w = 0.f;
    if (n < 384) {
        int e = n >> 6, j = n & 63;
        w = (e < 2) ? sw1[((size_t)e * D_IN + k) * 64 + j]
                    : gw1[((size_t)(e - 2) * D_IN + k) * 64 + j];
    } else if (n < 480) {
        int m = n - 384, s = m >> 5, j = m & 31;
        w = (s == 0) ? sgw1[k * 32 + j]
                     : ggw1[((size_t)(s - 1) * D_IN + k) * 32 + j];
    }
    __nv_bfloat16 hi = __float2bfloat16_rn(w);
    g_wthi[idx] = hi;
    g_wtlo[idx] = __float2bfloat16_rn(w - __bfloat162float(hi));
    if (idx < NCATP) {
        float b = 0.f;
        if (idx < 384) {
            int e = idx >> 6, j = idx & 63;
            b = (e < 2) ? sb1[e * 64 + j] : gb1[(e - 2) * 64 + j];
        } else if (idx < 480) {
            int m = idx - 384, s = m >> 5, j = m & 31;
            b = (s == 0) ? sgb1[j] : ggb1[(s - 1) * GH + j];
        }
        g_bc[idx] = b;
    }
}

// ---------------------------------------------------------------------------
// Kernel: H^T = silu(v @ W + b)^T via mma.sync bf16 split (3 passes),
// 2-stage cp.async pipeline, K chunks of 32.
// CTA 128x128, warps 2(M)x4(N).
// ---------------------------------------------------------------------------
#define KCH2    32
#define RS2     80                          // bytes per smem row (64 + 16 pad)
#define OPB     (128 * RS2)                 // 10240 per operand per stage
#define STAGE_B (4 * OPB)                   // 40960
#define SMO_BIAS (2 * STAGE_B)              // 81920
#define GEMM_SMEM (SMO_BIAS + 512)
#define STG_STRIDE 136                      // floats, epilogue stage [col][row]
#define NCHUNK  (D_IN / KCH2)               // 16

#define CPASYNC16(dst, src) \
    asm volatile("cp.async.cg.shared.global [%0], [%1], 16;" :: "r"(dst), "l"(src))

__device__ __forceinline__ void ldsm_x4(uint32_t* r, uint32_t a) {
    asm volatile("ldmatrix.sync.aligned.m8n8.x4.shared.b16 {%0,%1,%2,%3}, [%4];"
                 : "=r"(r[0]), "=r"(r[1]), "=r"(r[2]), "=r"(r[3]) : "r"(a));
}
__device__ __forceinline__ void mma_bf16(float* c, const uint32_t* a, uint32_t b0, uint32_t b1) {
    asm volatile(
        "mma.sync.aligned.m16n8k16.row.col.f32.bf16.bf16.f32 "
        "{%0,%1,%2,%3}, {%4,%5,%6,%7}, {%8,%9}, {%0,%1,%2,%3};"
        : "+f"(c[0]), "+f"(c[1]), "+f"(c[2]), "+f"(c[3])
        : "r"(a[0]), "r"(a[1]), "r"(a[2]), "r"(a[3]), "r"(b0), "r"(b1));
}

__global__ void __launch_bounds__(256, 2) gemm1_mma_kernel() {
    extern __shared__ char smem[];
    const uint32_t sb = smem_u32(smem);
    const int tid  = threadIdx.x;
    const int lane = tid & 31;
    const int warp = tid >> 5;
    const int wm = warp >> 2;
    const int wn = warp & 3;
    const int bm = blockIdx.y * 128;
    const int bn = blockIdx.x * 128;

    if (tid < 128) ((float*)(smem + SMO_BIAS))[tid] = g_bc[bn + tid];

    const int r0 = tid >> 2, r1 = (tid + 256) >> 2;
    const int s4 = (tid & 3) * 16;

    const int mi = lane >> 3;
    const int a_row = (lane & 7) + ((mi & 1) << 3);
    const int a_kb  = (mi >= 2) ? 16 : 0;
    const int b_row = (lane & 7) + ((mi >= 2) ? 8 : 0);
    const int b_kb  = (mi & 1) ? 16 : 0;

    float acc[4][4][4];
#pragma unroll
    for (int i = 0; i < 4; i++)
#pragma unroll
        for (int j = 0; j < 4; j++)
#pragma unroll
            for (int u = 0; u < 4; u++) acc[i][j][u] = 0.f;

    auto load_chunk = [&](int ch, int stg) {
        const int k0 = ch * KCH2;
        const uint32_t base = sb + stg * STAGE_B;
        const __nv_bfloat16* sa0 = g_vhi  + (size_t)(bm + r0) * D_IN + k0 + (s4 >> 1);
        const __nv_bfloat16* sa1 = g_vhi  + (size_t)(bm + r1) * D_IN + k0 + (s4 >> 1);
        const __nv_bfloat16* sb0 = g_wthi + (size_t)(bn + r0) * D_IN + k0 + (s4 >> 1);
        const __nv_bfloat16* sb1_ = g_wthi + (size_t)(bn + r1) * D_IN + k0 + (s4 >> 1);
        uint32_t d0 = r0 * RS2 + s4, d1 = r1 * RS2 + s4;
        CPASYNC16(base + 0 * OPB + d0, sa0);
        CPASYNC16(base + 0 * OPB + d1, sa1);
        CPASYNC16(base + 1 * OPB + d0, sa0 + (g_vlo - g_vhi));
        CPASYNC16(base + 1 * OPB + d1, sa1 + (g_vlo - g_vhi));
        CPASYNC16(base + 2 * OPB + d0, sb0);
        CPASYNC16(base + 2 * OPB + d1, sb1_);
        CPASYNC16(base + 3 * OPB + d0, sb0 + (g_wtlo - g_wthi));
        CPASYNC16(base + 3 * OPB + d1, sb1_ + (g_wtlo - g_wthi));
    };

    load_chunk(0, 0);
    asm volatile("cp.async.commit_group;");

    for (int ch = 0; ch < NCHUNK; ch++) {
        const int cur = ch & 1;
        if (ch + 1 < NCHUNK) {
            load_chunk(ch + 1, (ch + 1) & 1);
            asm volatile("cp.async.commit_group;");
            asm volatile("cp.async.wait_group 1;");
        } else {
            asm volatile("cp.async.wait_group 0;");
        }
        __syncthreads();

        const uint32_t stgb = sb + cur * STAGE_B;
        const uint32_t aAddr0 = stgb + 0 * OPB + (wm * 64 + a_row) * RS2 + a_kb;
        const uint32_t alAdd  = 1 * OPB;
        const uint32_t bAddr0 = stgb + 2 * OPB + (wn * 32 + b_row) * RS2 + b_kb;
        const uint32_t blAdd  = 1 * OPB;

#pragma unroll
        for (int kt = 0; kt < 2; kt++) {
            const uint32_t ka = kt * 32;
            uint32_t ah[4][4], al[4][4], bh[2][4], bl[2][4];
#pragma unroll
            for (int mt = 0; mt < 4; mt++)
                ldsm_x4(ah[mt], aAddr0 + mt * (16 * RS2) + ka);
#pragma unroll
            for (int h = 0; h < 2; h++)
                ldsm_x4(bh[h], bAddr0 + h * (16 * RS2) + ka);
#pragma unroll
            for (int mt = 0; mt < 4; mt++)
#pragma unroll
                for (int nt = 0; nt < 4; nt++)
                    mma_bf16(acc[mt][nt], ah[mt], bh[nt >> 1][(nt & 1) * 2], bh[nt >> 1][(nt & 1) * 2 + 1]);
#pragma unroll
            for (int h = 0; h < 2; h++)
                ldsm_x4(bl[h], bAddr0 + blAdd + h * (16 * RS2) + ka);
#pragma unroll
            for (int mt = 0; mt < 4; mt++)
#pragma unroll
                for (int nt = 0; nt < 4; nt++)
                    mma_bf16(acc[mt][nt], ah[mt], bl[nt >> 1][(nt & 1) * 2], bl[nt >> 1][(nt & 1) * 2 + 1]);
#pragma unroll
            for (int mt = 0; mt < 4; mt++)
                ldsm_x4(al[mt], aAddr0 + alAdd + mt * (16 * RS2) + ka);
#pragma unroll
            for (int mt = 0; mt < 4; mt++)
#pragma unroll
                for (int nt = 0; nt < 4; nt++)
                    mma_bf16(acc[mt][nt], al[mt], bh[nt >> 1][(nt & 1) * 2], bh[nt >> 1][(nt & 1) * 2 + 1]);
        }
        __syncthreads();
    }

    // Epilogue: bias + silu -> smem stage [col][row] -> coalesced g_HT writes
    {
        float* stg = (float*)smem;
        const float* bias = (const float*)(smem + SMO_BIAS);
#pragma unroll
        for (int mt = 0; mt < 4; mt++) {
#pragma unroll
            for (int nt = 0; nt < 4; nt++) {
#pragma unroll
                for (int u = 0; u < 4; u++) {
                    int row = wm * 64 + mt * 16 + (lane >> 2) + ((u >> 1) << 3);
                    int col = wn * 32 + nt * 8 + 2 * (lane & 3) + (u & 1);
                    float x = acc[mt][nt][u] + bias[col];
                    stg[col * STG_STRIDE + row] = x / (1.f + __expf(-x));
                }
            }
        }
        __syncthreads();
#pragma unroll
        for (int cl = 0; cl < 16; cl++) {
            int col = warp * 16 + cl;
            int gc = bn + col;
            if (gc < NCAT) {
                float4 val = *(float4*)&stg[col * STG_STRIDE + lane * 4];
                *(float4*)(g_HT + (size_t)gc * B_TOK + bm + lane * 4) = val;
            }
        }
    }
}

// ---------------------------------------------------------------------------
// Kernel: tail4 — slot-per-CTA, HALF-token-per-thread (2 threads/token).
// 128 threads = 64 tokens. grid (B/64, 3). Pair exchange via shfl_xor(1).
// Accumulates slot output in smem zs (owner-thread RMW), writes out directly.
// ---------------------------------------------------------------------------
#define T4_W2   0                        // 2*2048
#define T4_W3   4096                     // 2*2048
#define T4_B2   8192                     // 2*32
#define T4_B3   8256                     // 2*64
#define T4_GM   8384                     // 2*64
#define T4_BT   8512                     // 2*64
#define T4_GW   8640                     // 64
#define T4_GB   8704                     // 8 (2 used)
#define T4_ZS   8712                     // 64*68
#define T4_FLOATS (T4_ZS + 64 * 68)
#define T4_SMEM (T4_FLOATS * 4)

__global__ __launch_bounds__(128) void tail4_kernel(
    const float* __restrict__ sw2, const float* __restrict__ sb2,
    const float* __restrict__ sw3, const float* __restrict__ sb3,
    const float* __restrict__ sgam, const float* __restrict__ sbet,
    const float* __restrict__ sgw2, const float* __restrict__ sgb2,
    const float* __restrict__ gw2, const float* __restrict__ gb2,
    const float* __restrict__ gw3, const float* __restrict__ gb3,
    const float* __restrict__ ggam, const float* __restrict__ gbet,
    const float* __restrict__ ggw2, const float* __restrict__ ggb2,
    float* __restrict__ out) {
    extern __shared__ float sm[];
    const unsigned FULL = 0xffffffffu;

    const int p    = blockIdx.y;         // 0=group0(e2,3) 1=group1(e4,5) 2=shared(e0,1)
    const int tid  = threadIdx.x;
    const int half = tid & 1;
    const int ltok = tid >> 1;           // 0..63
    const int t0   = blockIdx.x * 64;
    const int tok  = t0 + ltok;
    const int e_base = (p == 2) ? 0 : ((p == 0) ? 2 : 4);
    const int gslot  = (p == 2) ? 0 : (p + 1);

    // --- stage weights for both experts of this slot ---
#pragma unroll
    for (int s = 0; s < 2; s++) {
        const int e = e_base + s;
        const float* w2src = (e < 2) ? (sw2 + (size_t)e * 2048) : (gw2 + (size_t)(e - 2) * 2048);
        const float* w3src = (e < 2) ? (sw3 + (size_t)e * 2048) : (gw3 + (size_t)(e - 2) * 2048);
        for (int i = tid; i < 2048; i += 128) {
            sm[T4_W2 + s * 2048 + i] = w2src[i];
            sm[T4_W3 + s * 2048 + i] = w3src[i];
        }
        if (tid < H2) sm[T4_B2 + s * 32 + tid] = (e < 2) ? sb2[e * 32 + tid] : gb2[(e - 2) * 32 + tid];
        if (tid < D_OUT) {
            sm[T4_B3 + s * 64 + tid] = (e < 2) ? sb3[e * 64 + tid]  : gb3[(e - 2) * 64 + tid];
            sm[T4_GM + s * 64 + tid] = (e < 2) ? sgam[e * 64 + tid] : ggam[(e - 2) * 64 + tid];
            sm[T4_BT + s * 64 + tid] = (e < 2) ? sbet[e * 64 + tid] : gbet[(e - 2) * 64 + tid];
        }
    }
    if (tid < 64) sm[T4_GW + tid] = (gslot == 0) ? sgw2[tid] : ggw2[(gslot - 1) * 64 + tid];
    if (tid < 2)  sm[T4_GB + tid] = (gslot == 0) ? sgb2[tid] : ggb2[(gslot - 1) * 2 + tid];
    __syncthreads();

    // --- gate softmax (both threads of pair compute identically) ---
    float wgate2[2];
    {
        float l0 = sm[T4_GB + 0], l1 = sm[T4_GB + 1];
        const float* gbase = g_HT + (size_t)(384 + gslot * 32) * B_TOK + tok;
#pragma unroll 8
        for (int i = 0; i < GH; i++) {
            float hg = gbase[(size_t)i * B_TOK];
            l0 += hg * sm[T4_GW + i * 2];
            l1 += hg * sm[T4_GW + i * 2 + 1];
        }
        float mx = fmaxf(l0, l1);
        float ea = __expf(l0 - mx), eb = __expf(l1 - mx);
        float inv_s = 1.f / (ea + eb);
        wgate2[0] = ea * inv_s;
        wgate2[1] = eb * inv_s;
    }

    float* zrow = sm + T4_ZS + ltok * 68 + half * 32;

#pragma unroll
    for (int s = 0; s < 2; s++) {
        const float* hbase = g_HT + (size_t)((e_base + s) * 64) * B_TOK + tok;
        const float* w2b = sm + T4_W2 + s * 2048 + half * 16;

        // layer 2 (this half's 16 h2 dims)
        float h2[16];
        {
            const float* b2 = sm + T4_B2 + s * 32 + half * 16;
#pragma unroll
            for (int j = 0; j < 16; j++) h2[j] = b2[j];
        }
#pragma unroll 8
        for (int i = 0; i < H1; i++) {
            float a = hbase[(size_t)i * B_TOK];
            const float4* w4 = (const float4*)(w2b + i * 32);
#pragma unroll
            for (int j4 = 0; j4 < 4; j4++) {
                float4 w = w4[j4];
                h2[j4 * 4 + 0] += a * w.x;
                h2[j4 * 4 + 1] += a * w.y;
                h2[j4 * 4 + 2] += a * w.z;
                h2[j4 * 4 + 3] += a * w.w;
            }
        }
#pragma unroll
        for (int j = 0; j < 16; j++) h2[j] = h2[j] / (1.f + __expf(-h2[j]));

        // exchange halves: build full h2 ordered [0..15]=hlo, [16..31]=hhi
        float hlo[16], hhi[16];
#pragma unroll
        for (int j = 0; j < 16; j++) {
            float other = __shfl_xor_sync(FULL, h2[j], 1);
            hlo[j] = half ? other : h2[j];
            hhi[j] = half ? h2[j] : other;
        }

        // layer 3 (this half's 32 output dims)
        float o[32];
        {
            const float* b3 = sm + T4_B3 + s * 64 + half * 32;
#pragma unroll
            for (int j = 0; j < 32; j++) o[j] = b3[j];
        }
        const float* w3b = sm + T4_W3 + s * 2048 + half * 32;
#pragma unroll
        for (int k = 0; k < 16; k++) {
            float h = hlo[k];
            const float4* w4 = (const float4*)(w3b + k * 64);
#pragma unroll
            for (int j4 = 0; j4 < 8; j4++) {
                float4 w = w4[j4];
                o[j4 * 4 + 0] += h * w.x;
                o[j4 * 4 + 1] += h * w.y;
                o[j4 * 4 + 2] += h * w.z;
                o[j4 * 4 + 3] += h * w.w;
            }
        }
#pragma unroll
        for (int k = 0; k < 16; k++) {
            float h = hhi[k];
            const float4* w4 = (const float4*)(w3b + (k + 16) * 64);
#pragma unroll
            for (int j4 = 0; j4 < 8; j4++) {
                float4 w = w4[j4];
                o[j4 * 4 + 0] += h * w.x;
                o[j4 * 4 + 1] += h * w.y;
                o[j4 * 4 + 2] += h * w.z;
                o[j4 * 4 + 3] += h * w.w;
            }
        }

        // LayerNorm across the pair
        float s1 = 0.f;
#pragma unroll
        for (int j = 0; j < 32; j++) s1 += o[j];
        s1 += __shfl_xor_sync(FULL, s1, 1);
        float mu = s1 * (1.f / 64.f);
        float s2 = 0.f;
#pragma unroll
        for (int j = 0; j < 32; j++) { float d = o[j] - mu; s2 += d * d; }
        s2 += __shfl_xor_sync(FULL, s2, 1);
        float x = s2 * (1.f / 64.f) + LN_EPS;
        float rinv = rsqrtf(x);
        rinv = rinv * (1.5f - 0.5f * x * rinv * rinv);

        const float wg = wgate2[s];
        const float* gm = sm + T4_GM + s * 64 + half * 32;
        const float* bt = sm + T4_BT + s * 64 + half * 32;
        if (s == 0) {
#pragma unroll
            for (int j4 = 0; j4 < 8; j4++) {
                float4 y;
                float* yy = (float*)&y;
#pragma unroll
                for (int u = 0; u < 4; u++) {
                    int j = j4 * 4 + u;
                    yy[u] = wg * (gm[j] * (o[j] - mu) * rinv + bt[j]);
                }
                *(float4*)(zrow + j4 * 4) = y;
            }
        } else {
#pragma unroll
            for (int j4 = 0; j4 < 8; j4++) {
                float4 z = *(float4*)(zrow + j4 * 4);
#pragma unroll
                for (int u = 0; u < 4; u++) {
                    int j = j4 * 4 + u;
                    ((float*)&z)[u] += wg * (gm[j] * (o[j] - mu) * rinv + bt[j]);
                }
                *(float4*)(zrow + j4 * 4) = z;
            }
        }
    }
    __syncthreads();

    // coalesced final store: out[p][t0..t0+63][0..63]
    float* obase = out + ((size_t)p * B_TOK + t0) * D_OUT;
#pragma unroll
    for (int r = 0; r < 8; r++) {
        int lin = tid + r * 128;             // over 1024 float4
        int tw = lin >> 4;                   // token in tile
        int j4 = lin & 15;
        float4 val = *(float4*)(sm + T4_ZS + tw * 68 + j4 * 4);
        *(float4*)(obase + (size_t)tw * D_OUT + j4 * 4) = val;
    }
}

// ---------------------------------------------------------------------------
// Launch
// ---------------------------------------------------------------------------
extern "C" void kernel_launch(void* const* d_in, const int* in_sizes, int n_in,
                              void* d_out, int out_size) {
    (void)in_sizes; (void)n_in; (void)out_size;
    const float* v    = (const float*)d_in[0];
    const float* sw1  = (const float*)d_in[1];
    const float* sb1  = (const float*)d_in[2];
    const float* sw2  = (const float*)d_in[3];
    const float* sb2  = (const float*)d_in[4];
    const float* sw3  = (const float*)d_in[5];
    const float* sb3  = (const float*)d_in[6];
    const float* sgam = (const float*)d_in[7];
    const float* sbet = (const float*)d_in[8];
    const float* sgw1 = (const float*)d_in[9];
    const float* sgb1 = (const float*)d_in[10];
    const float* sgw2 = (const float*)d_in[11];
    const float* sgb2 = (const float*)d_in[12];
    const float* gw1  = (const float*)d_in[13];
    const float* gb1  = (const float*)d_in[14];
    const float* gw2  = (const float*)d_in[15];
    const float* gb2  = (const float*)d_in[16];
    const float* gw3  = (const float*)d_in[17];
    const float* gb3  = (const float*)d_in[18];
    const float* ggam = (const float*)d_in[19];
    const float* gbet = (const float*)d_in[20];
    const float* ggw1 = (const float*)d_in[21];
    const float* ggb1 = (const float*)d_in[22];
    const float* ggw2 = (const float*)d_in[23];
    const float* ggb2 = (const float*)d_in[24];
    float* out = (float*)d_out;

    conv_v_kernel<<<(B_TOK * D_IN / 4 + 255) / 256, 256>>>(v);
    pack_w_kernel<<<(NCATP * D_IN + 255) / 256, 256>>>(sw1, sb1, gw1, gb1, sgw1, sgb1, ggw1, ggb1);

    cudaFuncSetAttribute(gemm1_mma_kernel, cudaFuncAttributeMaxDynamicSharedMemorySize, GEMM_SMEM);
    dim3 g1(NCATP / 128, B_TOK / 128);
    gemm1_mma_kernel<<<g1, 256, GEMM_SMEM>>>();

    cudaFuncSetAttribute(tail4_kernel, cudaFuncAttributeMaxDynamicSharedMemorySize, T4_SMEM);
    dim3 g2(B_TOK / 64, 3);
    tail4_kernel<<<g2, 128, T4_SMEM>>>(sw2, sb2, sw3, sb3, sgam, sbet, sgw2, sgb2,
                                       gw2, gb2, gw3, gb3, ggam, gbet, ggw2, ggb2, out);
}

// round 7
// speedup vs baseline: 1.0944x; 1.0226x over previous
#include <cuda_runtime.h>
#include <cuda_bf16.h>
#include <math.h>
#include <stddef.h>
#include <stdint.h>

// ---------------------------------------------------------------------------
// Problem constants
// ---------------------------------------------------------------------------
#define B_TOK   16384
#define D_IN    512
#define D_OUT   64
#define H1      64
#define H2      32
#define GH      32
#define NEXP    6
#define NCAT    480
#define NCATP   512
#define LN_EPS  1e-5f

// ---------------------------------------------------------------------------
// Device scratch
// ---------------------------------------------------------------------------
__device__ __align__(16) __nv_bfloat16 g_vhi[(size_t)B_TOK * D_IN];
__device__ __align__(16) __nv_bfloat16 g_vlo[(size_t)B_TOK * D_IN];
__device__ __align__(16) __nv_bfloat16 g_wthi[NCATP * D_IN];   // [n][k]
__device__ __align__(16) __nv_bfloat16 g_wtlo[NCATP * D_IN];
__device__ float g_bc[NCATP];
__device__ __align__(16) float g_HT[(size_t)NCATP * B_TOK];    // H transposed [col][token]

__device__ __forceinline__ uint32_t smem_u32(const void* p) {
    uint32_t a;
    asm("{ .reg .u64 t; cvta.to.shared.u64 t, %1; cvt.u32.u64 %0, t; }" : "=r"(a) : "l"(p));
    return a;
}

// ---------------------------------------------------------------------------
// Kernel: convert v -> bf16 hi/lo (error-free split)
// ---------------------------------------------------------------------------
__global__ __launch_bounds__(256) void conv_v_kernel(const float* __restrict__ v) {
    size_t i = ((size_t)blockIdx.x * 256 + threadIdx.x) * 4;
    float4 x = *(const float4*)(v + i);
    __nv_bfloat16 h0 = __float2bfloat16_rn(x.x), h1 = __float2bfloat16_rn(x.y);
    __nv_bfloat16 h2 = __float2bfloat16_rn(x.z), h3 = __float2bfloat16_rn(x.w);
    __nv_bfloat16 l0 = __float2bfloat16_rn(x.x - __bfloat162float(h0));
    __nv_bfloat16 l1 = __float2bfloat16_rn(x.y - __bfloat162float(h1));
    __nv_bfloat16 l2 = __float2bfloat16_rn(x.z - __bfloat162float(h2));
    __nv_bfloat16 l3 = __float2bfloat16_rn(x.w - __bfloat162float(h3));
    __nv_bfloat162* ph = (__nv_bfloat162*)(g_vhi + i);
    __nv_bfloat162* pl = (__nv_bfloat162*)(g_vlo + i);
    ph[0] = __nv_bfloat162(h0, h1); ph[1] = __nv_bfloat162(h2, h3);
    pl[0] = __nv_bfloat162(l0, l1); pl[1] = __nv_bfloat162(l2, l3);
}

// ---------------------------------------------------------------------------
// Kernel: pack transposed layer-1 weights [n][k] bf16 hi/lo + bias (padded)
// ---------------------------------------------------------------------------
__global__ __launch_bounds__(256) void pack_w_kernel(
    const float* __restrict__ sw1, const float* __restrict__ sb1,
    const float* __restrict__ gw1, const float* __restrict__ gb1,
    const float* __restrict__ sgw1, const float* __restrict__ sgb1,
    const float* __restrict__ ggw1, const float* __restrict__ ggb1) {
    int idx = blockIdx.x * 256 + threadIdx.x;   // over 512*512
    int n = idx >> 9, k = idx & 511;
    float w = 0.f;
    if (n < 384) {
        int e = n >> 6, j = n & 63;
        w = (e < 2) ? sw1[((size_t)e * D_IN + k) * 64 + j]
                    : gw1[((size_t)(e - 2) * D_IN + k) * 64 + j];
    } else if (n < 480) {
        int m = n - 384, s = m >> 5, j = m & 31;
        w = (s == 0) ? sgw1[k * 32 + j]
                     : ggw1[((size_t)(s - 1) * D_IN + k) * 32 + j];
    }
    __nv_bfloat16 hi = __float2bfloat16_rn(w);
    g_wthi[idx] = hi;
    g_wtlo[idx] = __float2bfloat16_rn(w - __bfloat162float(hi));
    if (idx < NCATP) {
        float b = 0.f;
        if (idx < 384) {
            int e = idx >> 6, j = idx & 63;
            b = (e < 2) ? sb1[e * 64 + j] : gb1[(e - 2) * 64 + j];
        } else if (idx < 480) {
            int m = idx - 384, s = m >> 5, j = m & 31;
            b = (s == 0) ? sgb1[j] : ggb1[(s - 1) * GH + j];
        }
        g_bc[idx] = b;
    }
}

// ---------------------------------------------------------------------------
// Kernel: H^T = silu(v @ W + b)^T via mma.sync bf16 split (3 passes),
// 2-stage cp.async pipeline, K chunks of 32. (unchanged from R6)
// ---------------------------------------------------------------------------
#define KCH2    32
#define RS2     80
#define OPB     (128 * RS2)
#define STAGE_B (4 * OPB)
#define SMO_BIAS (2 * STAGE_B)
#define GEMM_SMEM (SMO_BIAS + 512)
#define STG_STRIDE 136
#define NCHUNK  (D_IN / KCH2)

#define CPASYNC16(dst, src) \
    asm volatile("cp.async.cg.shared.global [%0], [%1], 16;" :: "r"(dst), "l"(src))

__device__ __forceinline__ void ldsm_x4(uint32_t* r, uint32_t a) {
    asm volatile("ldmatrix.sync.aligned.m8n8.x4.shared.b16 {%0,%1,%2,%3}, [%4];"
                 : "=r"(r[0]), "=r"(r[1]), "=r"(r[2]), "=r"(r[3]) : "r"(a));
}
__device__ __forceinline__ void mma_bf16(float* c, const uint32_t* a, uint32_t b0, uint32_t b1) {
    asm volatile(
        "mma.sync.aligned.m16n8k16.row.col.f32.bf16.bf16.f32 "
        "{%0,%1,%2,%3}, {%4,%5,%6,%7}, {%8,%9}, {%0,%1,%2,%3};"
        : "+f"(c[0]), "+f"(c[1]), "+f"(c[2]), "+f"(c[3])
        : "r"(a[0]), "r"(a[1]), "r"(a[2]), "r"(a[3]), "r"(b0), "r"(b1));
}

__global__ void __launch_bounds__(256, 2) gemm1_mma_kernel() {
    extern __shared__ char smem[];
    const uint32_t sb = smem_u32(smem);
    const int tid  = threadIdx.x;
    const int lane = tid & 31;
    const int warp = tid >> 5;
    const int wm = warp >> 2;
    const int wn = warp & 3;
    const int bm = blockIdx.y * 128;
    const int bn = blockIdx.x * 128;

    if (tid < 128) ((float*)(smem + SMO_BIAS))[tid] = g_bc[bn + tid];

    const int r0 = tid >> 2, r1 = (tid + 256) >> 2;
    const int s4 = (tid & 3) * 16;

    const int mi = lane >> 3;
    const int a_row = (lane & 7) + ((mi & 1) << 3);
    const int a_kb  = (mi >= 2) ? 16 : 0;
    const int b_row = (lane & 7) + ((mi >= 2) ? 8 : 0);
    const int b_kb  = (mi & 1) ? 16 : 0;

    float acc[4][4][4];
#pragma unroll
    for (int i = 0; i < 4; i++)
#pragma unroll
        for (int j = 0; j < 4; j++)
#pragma unroll
            for (int u = 0; u < 4; u++) acc[i][j][u] = 0.f;

    auto load_chunk = [&](int ch, int stg) {
        const int k0 = ch * KCH2;
        const uint32_t base = sb + stg * STAGE_B;
        const __nv_bfloat16* sa0 = g_vhi  + (size_t)(bm + r0) * D_IN + k0 + (s4 >> 1);
        const __nv_bfloat16* sa1 = g_vhi  + (size_t)(bm + r1) * D_IN + k0 + (s4 >> 1);
        const __nv_bfloat16* sb0 = g_wthi + (size_t)(bn + r0) * D_IN + k0 + (s4 >> 1);
        const __nv_bfloat16* sb1_ = g_wthi + (size_t)(bn + r1) * D_IN + k0 + (s4 >> 1);
        uint32_t d0 = r0 * RS2 + s4, d1 = r1 * RS2 + s4;
        CPASYNC16(base + 0 * OPB + d0, sa0);
        CPASYNC16(base + 0 * OPB + d1, sa1);
        CPASYNC16(base + 1 * OPB + d0, sa0 + (g_vlo - g_vhi));
        CPASYNC16(base + 1 * OPB + d1, sa1 + (g_vlo - g_vhi));
        CPASYNC16(base + 2 * OPB + d0, sb0);
        CPASYNC16(base + 2 * OPB + d1, sb1_);
        CPASYNC16(base + 3 * OPB + d0, sb0 + (g_wtlo - g_wthi));
        CPASYNC16(base + 3 * OPB + d1, sb1_ + (g_wtlo - g_wthi));
    };

    load_chunk(0, 0);
    asm volatile("cp.async.commit_group;");

    for (int ch = 0; ch < NCHUNK; ch++) {
        const int cur = ch & 1;
        if (ch + 1 < NCHUNK) {
            load_chunk(ch + 1, (ch + 1) & 1);
            asm volatile("cp.async.commit_group;");
            asm volatile("cp.async.wait_group 1;");
        } else {
            asm volatile("cp.async.wait_group 0;");
        }
        __syncthreads();

        const uint32_t stgb = sb + cur * STAGE_B;
        const uint32_t aAddr0 = stgb + 0 * OPB + (wm * 64 + a_row) * RS2 + a_kb;
        const uint32_t alAdd  = 1 * OPB;
        const uint32_t bAddr0 = stgb + 2 * OPB + (wn * 32 + b_row) * RS2 + b_kb;
        const uint32_t blAdd  = 1 * OPB;

#pragma unroll
        for (int kt = 0; kt < 2; kt++) {
            const uint32_t ka = kt * 32;
            uint32_t ah[4][4], al[4][4], bh[2][4], bl[2][4];
#pragma unroll
            for (int mt = 0; mt < 4; mt++)
                ldsm_x4(ah[mt], aAddr0 + mt * (16 * RS2) + ka);
#pragma unroll
            for (int h = 0; h < 2; h++)
                ldsm_x4(bh[h], bAddr0 + h * (16 * RS2) + ka);
#pragma unroll
            for (int mt = 0; mt < 4; mt++)
#pragma unroll
                for (int nt = 0; nt < 4; nt++)
                    mma_bf16(acc[mt][nt], ah[mt], bh[nt >> 1][(nt & 1) * 2], bh[nt >> 1][(nt & 1) * 2 + 1]);
#pragma unroll
            for (int h = 0; h < 2; h++)
                ldsm_x4(bl[h], bAddr0 + blAdd + h * (16 * RS2) + ka);
#pragma unroll
            for (int mt = 0; mt < 4; mt++)
#pragma unroll
                for (int nt = 0; nt < 4; nt++)
                    mma_bf16(acc[mt][nt], ah[mt], bl[nt >> 1][(nt & 1) * 2], bl[nt >> 1][(nt & 1) * 2 + 1]);
#pragma unroll
            for (int mt = 0; mt < 4; mt++)
                ldsm_x4(al[mt], aAddr0 + alAdd + mt * (16 * RS2) + ka);
#pragma unroll
            for (int mt = 0; mt < 4; mt++)
#pragma unroll
                for (int nt = 0; nt < 4; nt++)
                    mma_bf16(acc[mt][nt], al[mt], bh[nt >> 1][(nt & 1) * 2], bh[nt >> 1][(nt & 1) * 2 + 1]);
        }
        __syncthreads();
    }

    // Epilogue: bias + silu -> smem stage [col][row] -> coalesced g_HT writes
    {
        float* stg = (float*)smem;
        const float* bias = (const float*)(smem + SMO_BIAS);
#pragma unroll
        for (int mt = 0; mt < 4; mt++) {
#pragma unroll
            for (int nt = 0; nt < 4; nt++) {
#pragma unroll
                for (int u = 0; u < 4; u++) {
                    int row = wm * 64 + mt * 16 + (lane >> 2) + ((u >> 1) << 3);
                    int col = wn * 32 + nt * 8 + 2 * (lane & 3) + (u & 1);
                    float x = acc[mt][nt][u] + bias[col];
                    stg[col * STG_STRIDE + row] = x / (1.f + __expf(-x));
                }
            }
        }
        __syncthreads();
#pragma unroll
        for (int cl = 0; cl < 16; cl++) {
            int col = warp * 16 + cl;
            int gc = bn + col;
            if (gc < NCAT) {
                float4 val = *(float4*)&stg[col * STG_STRIDE + lane * 4];
                *(float4*)(g_HT + (size_t)gc * B_TOK + bm + lane * 4) = val;
            }
        }
    }
}

// ---------------------------------------------------------------------------
// Kernel: tail5 — slot-per-CTA, 256 threads, 128 tokens, 2 threads/token.
// h1 for BOTH experts staged in smem (coalesced); z kept in registers across
// experts; direct store to out. grid (B/128, 3).
// ---------------------------------------------------------------------------
// smem floats:
#define T5_H1   0                         // 2*64*128 = 16384
#define T5_W2   16384                     // 2*2048
#define T5_W3   20480                     // 2*2048
#define T5_B2   24576                     // 2*32
#define T5_B3   24640                     // 2*64
#define T5_GM   24768                     // 2*64
#define T5_BT   24896                     // 2*64
#define T5_GW   25024                     // 64
#define T5_GB   25088                     // 2
#define T5_FLOATS 25090
#define T5_SMEM (T5_FLOATS * 4)

__global__ void __launch_bounds__(256, 2) tail5_kernel(
    const float* __restrict__ sw2, const float* __restrict__ sb2,
    const float* __restrict__ sw3, const float* __restrict__ sb3,
    const float* __restrict__ sgam, const float* __restrict__ sbet,
    const float* __restrict__ sgw2, const float* __restrict__ sgb2,
    const float* __restrict__ gw2, const float* __restrict__ gb2,
    const float* __restrict__ gw3, const float* __restrict__ gb3,
    const float* __restrict__ ggam, const float* __restrict__ gbet,
    const float* __restrict__ ggw2, const float* __restrict__ ggb2,
    float* __restrict__ out) {
    extern __shared__ float sm[];
    const unsigned FULL = 0xffffffffu;

    const int p    = blockIdx.y;          // 0=group0(e2,3) 1=group1(e4,5) 2=shared(e0,1)
    const int tid  = threadIdx.x;
    const int half = tid & 1;
    const int ltok = tid >> 1;            // 0..127
    const int t0   = blockIdx.x * 128;
    const int tok  = t0 + ltok;
    const int e_base = (p == 2) ? 0 : ((p == 0) ? 2 : 4);
    const int gslot  = (p == 2) ? 0 : (p + 1);

    // --- stage h1 rows for BOTH experts: rows (e_base*64 .. e_base*64+127) ---
    // 4096 float4, 16 per thread, coalesced per row (32 float4/row).
    {
        const float* src = g_HT + (size_t)(e_base * 64) * B_TOK + t0;
#pragma unroll
        for (int k = 0; k < 16; k++) {
            int lin = tid + k * 256;          // 0..4095
            int row = lin >> 5, q = lin & 31;
            float4 val = *(const float4*)(src + (size_t)row * B_TOK + q * 4);
            *(float4*)&sm[T5_H1 + row * 128 + q * 4] = val;
        }
    }
    // --- stage weights for both experts of this slot ---
#pragma unroll
    for (int s = 0; s < 2; s++) {
        const int e = e_base + s;
        const float* w2src = (e < 2) ? (sw2 + (size_t)e * 2048) : (gw2 + (size_t)(e - 2) * 2048);
        const float* w3src = (e < 2) ? (sw3 + (size_t)e * 2048) : (gw3 + (size_t)(e - 2) * 2048);
        for (int i = tid; i < 2048; i += 256) {
            sm[T5_W2 + s * 2048 + i] = w2src[i];
            sm[T5_W3 + s * 2048 + i] = w3src[i];
        }
        if (tid < H2) sm[T5_B2 + s * 32 + tid] = (e < 2) ? sb2[e * 32 + tid] : gb2[(e - 2) * 32 + tid];
        if (tid < D_OUT) {
            sm[T5_B3 + s * 64 + tid] = (e < 2) ? sb3[e * 64 + tid]  : gb3[(e - 2) * 64 + tid];
            sm[T5_GM + s * 64 + tid] = (e < 2) ? sgam[e * 64 + tid] : ggam[(e - 2) * 64 + tid];
            sm[T5_BT + s * 64 + tid] = (e < 2) ? sbet[e * 64 + tid] : gbet[(e - 2) * 64 + tid];
        }
    }
    if (tid < 64) sm[T5_GW + tid] = (gslot == 0) ? sgw2[tid] : ggw2[(gslot - 1) * 64 + tid];
    if (tid < 2)  sm[T5_GB + tid] = (gslot == 0) ? sgb2[tid] : ggb2[(gslot - 1) * 2 + tid];
    __syncthreads();

    // --- gate softmax (from global gate rows; coalesced, both halves same) ---
    float wgate2[2];
    {
        float l0 = sm[T5_GB + 0], l1 = sm[T5_GB + 1];
        const float* gbase = g_HT + (size_t)(384 + gslot * 32) * B_TOK + tok;
#pragma unroll 8
        for (int i = 0; i < GH; i++) {
            float hg = gbase[(size_t)i * B_TOK];
            l0 += hg * sm[T5_GW + i * 2];
            l1 += hg * sm[T5_GW + i * 2 + 1];
        }
        float mx = fmaxf(l0, l1);
        float ea = __expf(l0 - mx), eb = __expf(l1 - mx);
        float inv_s = 1.f / (ea + eb);
        wgate2[0] = ea * inv_s;
        wgate2[1] = eb * inv_s;
    }

    float z[32];

#pragma unroll
    for (int s = 0; s < 2; s++) {
        const float* h1b = sm + T5_H1 + s * 8192;
        const float* w2b = sm + T5_W2 + s * 2048 + half * 16;

        // layer 2 (this half's 16 h2 dims)
        float h2[16];
        {
            const float* b2 = sm + T5_B2 + s * 32 + half * 16;
#pragma unroll
            for (int j = 0; j < 16; j++) h2[j] = b2[j];
        }
#pragma unroll 8
        for (int i = 0; i < H1; i++) {
            float a = h1b[i * 128 + ltok];
            const float4* w4 = (const float4*)(w2b + i * 32);
#pragma unroll
            for (int j4 = 0; j4 < 4; j4++) {
                float4 w = w4[j4];
                h2[j4 * 4 + 0] += a * w.x;
                h2[j4 * 4 + 1] += a * w.y;
                h2[j4 * 4 + 2] += a * w.z;
                h2[j4 * 4 + 3] += a * w.w;
            }
        }
#pragma unroll
        for (int j = 0; j < 16; j++) h2[j] = h2[j] / (1.f + __expf(-h2[j]));

        // exchange halves: full h2 ordered [0..15]=lo-half, [16..31]=hi-half
        float hlo[16], hhi[16];
#pragma unroll
        for (int j = 0; j < 16; j++) {
            float other = __shfl_xor_sync(FULL, h2[j], 1);
            hlo[j] = half ? other : h2[j];
            hhi[j] = half ? h2[j] : other;
        }

        // layer 3 (this half's 32 output dims)
        float o[32];
        {
            const float* b3 = sm + T5_B3 + s * 64 + half * 32;
#pragma unroll
            for (int j = 0; j < 32; j++) o[j] = b3[j];
        }
        const float* w3b = sm + T5_W3 + s * 2048 + half * 32;
#pragma unroll
        for (int k = 0; k < 16; k++) {
            float h = hlo[k];
            const float4* w4 = (const float4*)(w3b + k * 64);
#pragma unroll
            for (int j4 = 0; j4 < 8; j4++) {
                float4 w = w4[j4];
                o[j4 * 4 + 0] += h * w.x;
                o[j4 * 4 + 1] += h * w.y;
                o[j4 * 4 + 2] += h * w.z;
                o[j4 * 4 + 3] += h * w.w;
            }
        }
#pragma unroll
        for (int k = 0; k < 16; k++) {
            float h = hhi[k];
            const float4* w4 = (const float4*)(w3b + (k + 16) * 64);
#pragma unroll
            for (int j4 = 0; j4 < 8; j4++) {
                float4 w = w4[j4];
                o[j4 * 4 + 0] += h * w.x;
                o[j4 * 4 + 1] += h * w.y;
                o[j4 * 4 + 2] += h * w.z;
                o[j4 * 4 + 3] += h * w.w;
            }
        }

        // LayerNorm across the pair
        float s1 = 0.f;
#pragma unroll
        for (int j = 0; j < 32; j++) s1 += o[j];
        s1 += __shfl_xor_sync(FULL, s1, 1);
        float mu = s1 * (1.f / 64.f);
        float s2 = 0.f;
#pragma unroll
        for (int j = 0; j < 32; j++) { float d = o[j] - mu; s2 += d * d; }
        s2 += __shfl_xor_sync(FULL, s2, 1);
        float x = s2 * (1.f / 64.f) + LN_EPS;
        float rinv = rsqrtf(x);
        rinv = rinv * (1.5f - 0.5f * x * rinv * rinv);

        const float wg = wgate2[s];
        const float* gm = sm + T5_GM + s * 64 + half * 32;
        const float* bt = sm + T5_BT + s * 64 + half * 32;
        if (s == 0) {
#pragma unroll
            for (int j = 0; j < 32; j++)
                z[j] = wg * (gm[j] * (o[j] - mu) * rinv + bt[j]);
        } else {
#pragma unroll
            for (int j = 0; j < 32; j++)
                z[j] += wg * (gm[j] * (o[j] - mu) * rinv + bt[j]);
        }
    }

    // direct store: out[p][tok][half*32 .. half*32+31]
    float* obase = out + ((size_t)p * B_TOK + tok) * D_OUT + half * 32;
#pragma unroll
    for (int j4 = 0; j4 < 8; j4++) {
        float4 y;
        y.x = z[j4 * 4 + 0]; y.y = z[j4 * 4 + 1];
        y.z = z[j4 * 4 + 2]; y.w = z[j4 * 4 + 3];
        *(float4*)(obase + j4 * 4) = y;
    }
}

// ---------------------------------------------------------------------------
// Launch
// ---------------------------------------------------------------------------
extern "C" void kernel_launch(void* const* d_in, const int* in_sizes, int n_in,
                              void* d_out, int out_size) {
    (void)in_sizes; (void)n_in; (void)out_size;
    const float* v    = (const float*)d_in[0];
    const float* sw1  = (const float*)d_in[1];
    const float* sb1  = (const float*)d_in[2];
    const float* sw2  = (const float*)d_in[3];
    const float* sb2  = (const float*)d_in[4];
    const float* sw3  = (const float*)d_in[5];
    const float* sb3  = (const float*)d_in[6];
    const float* sgam = (const float*)d_in[7];
    const float* sbet = (const float*)d_in[8];
    const float* sgw1 = (const float*)d_in[9];
    const float* sgb1 = (const float*)d_in[10];
    const float* sgw2 = (const float*)d_in[11];
    const float* sgb2 = (const float*)d_in[12];
    const float* gw1  = (const float*)d_in[13];
    const float* gb1  = (const float*)d_in[14];
    const float* gw2  = (const float*)d_in[15];
    const float* gb2  = (const float*)d_in[16];
    const float* gw3  = (const float*)d_in[17];
    const float* gb3  = (const float*)d_in[18];
    const float* ggam = (const float*)d_in[19];
    const float* gbet = (const float*)d_in[20];
    const float* ggw1 = (const float*)d_in[21];
    const float* ggb1 = (const float*)d_in[22];
    const float* ggw2 = (const float*)d_in[23];
    const float* ggb2 = (const float*)d_in[24];
    float* out = (float*)d_out;

    conv_v_kernel<<<(B_TOK * D_IN / 4 + 255) / 256, 256>>>(v);
    pack_w_kernel<<<(NCATP * D_IN + 255) / 256, 256>>>(sw1, sb1, gw1, gb1, sgw1, sgb1, ggw1, ggb1);

    cudaFuncSetAttribute(gemm1_mma_kernel, cudaFuncAttributeMaxDynamicSharedMemorySize, GEMM_SMEM);
    dim3 g1(NCATP / 128, B_TOK / 128);
    gemm1_mma_kernel<<<g1, 256, GEMM_SMEM>>>();

    cudaFuncSetAttribute(tail5_kernel, cudaFuncAttributeMaxDynamicSharedMemorySize, T5_SMEM);
    dim3 g2(B_TOK / 128, 3);
    tail5_kernel<<<g2, 256, T5_SMEM>>>(sw2, sb2, sw3, sb3, sgam, sbet, sgw2, sgb2,
                                       gw2, gb2, gw3, gb3, ggam, gbet, ggw2, ggb2, out);
}